// round 5
// baseline (speedup 1.0000x reference)
#include <cuda_runtime.h>
#include <cuda_fp16.h>
#include <cstdint>

#define NN 6144
#define NF 256
#define NH 4
#define ND 64
#define IT 48            // rows per CTA (6144/48 = 128 CTAs)
#define JT 64            // j-chunk
#define NCHUNK (NN/JT)   // 96
#define PST 72           // P smem row stride (halves), pad for ldmatrix
#define BST 88           // B smem row stride (halves), 72 cols + pad

// scratch (allowed: __device__ globals)
__device__ __half  g_ht16[NH*NN*ND];        // [h][n][d] fp16
__device__ float2  g_srcAC[NH*NN];          // (e^src, e^{0.2 src})
__device__ float4  g_tgtBD4[NH*NN/2];       // pairs of (e^tgt, e^{0.2 tgt})

__device__ __forceinline__ unsigned smem_u32(const void* p){
    return (unsigned)__cvta_generic_to_shared(p);
}

// ------------------------------------------------------------------
// kernel 1: ht = h @ W  (fp32 accum), store as fp16 into g_ht16
// grid (4, 96), block 256.  C tile 64(n) x 64(m=head*64+d)
// ------------------------------------------------------------------
__global__ void k1_gemm(const float* __restrict__ h, const float* __restrict__ W) {
    __shared__ float As[16][64];   // [k][n]
    __shared__ float Bs[16][64];   // [k][m]
    const int tid = threadIdx.x;
    const int tx = tid & 15, ty = tid >> 4;
    const int m0 = blockIdx.x * 64;
    const int n0 = blockIdx.y * 64;
    float acc[4][4] = {};
    for (int k0 = 0; k0 < NF; k0 += 16) {
        {   // load h tile, store transposed
            int n = tid >> 2, kq = tid & 3;
            float4 v = *reinterpret_cast<const float4*>(&h[(n0+n)*NF + k0 + kq*4]);
            As[kq*4+0][n] = v.x; As[kq*4+1][n] = v.y;
            As[kq*4+2][n] = v.z; As[kq*4+3][n] = v.w;
        }
        {   // load W tile
            int k = tid >> 4, mq = tid & 15;
            float4 v = *reinterpret_cast<const float4*>(&W[(k0+k)*NF + m0 + mq*4]);
            *reinterpret_cast<float4*>(&Bs[k][mq*4]) = v;
        }
        __syncthreads();
        #pragma unroll
        for (int kk = 0; kk < 16; kk++) {
            float4 a4 = *reinterpret_cast<const float4*>(&As[kk][ty*4]);
            float4 b4 = *reinterpret_cast<const float4*>(&Bs[kk][tx*4]);
            float av[4] = {a4.x,a4.y,a4.z,a4.w};
            float bv[4] = {b4.x,b4.y,b4.z,b4.w};
            #pragma unroll
            for (int i=0;i<4;i++)
                #pragma unroll
                for (int j=0;j<4;j++) acc[i][j] += av[i]*bv[j];
        }
        __syncthreads();
    }
    const int head = blockIdx.x;   // m-tile == head (64-aligned)
    #pragma unroll
    for (int i=0;i<4;i++){
        int n = n0 + ty*4 + i;
        __half* dst = &g_ht16[((size_t)head*NN + n)*ND + tx*4];
        #pragma unroll
        for (int j=0;j<4;j+=2){
            *reinterpret_cast<__half2*>(dst + j) = __floats2half2_rn(acc[i][j], acc[i][j+1]);
        }
    }
}

// ------------------------------------------------------------------
// kernel 2: per (head,node) logits -> 4 exps. One warp per pair.
// grid 3072, block 256 (8 warps)
// ------------------------------------------------------------------
__global__ void k2_srctgt(const float* __restrict__ a) {
    const int w = threadIdx.x >> 5, lane = threadIdx.x & 31;
    const int p = blockIdx.x * 8 + w;      // p = h*NN + n
    const int hh = p / NN;
    __half2 x = reinterpret_cast<const __half2*>(&g_ht16[(size_t)p*ND])[lane];
    float2 xf = __half22float2(x);
    float2 as = *reinterpret_cast<const float2*>(&a[hh*2*ND + 2*lane]);
    float2 at = *reinterpret_cast<const float2*>(&a[hh*2*ND + ND + 2*lane]);
    float s = xf.x*as.x + xf.y*as.y;
    float t = xf.x*at.x + xf.y*at.y;
    #pragma unroll
    for (int off = 16; off; off >>= 1){
        s += __shfl_xor_sync(0xffffffffu, s, off);
        t += __shfl_xor_sync(0xffffffffu, t, off);
    }
    if (lane == 0) {
        g_srcAC[p] = make_float2(expf(s), expf(0.2f*s));
        reinterpret_cast<float2*>(g_tgtBD4)[p] = make_float2(expf(t), expf(0.2f*t));
    }
}

// ------------------------------------------------------------------
// kernel 3: flash-style GAT. grid 128, block 256 (8 warps).
// warp w: head = w&3, n-set = w>>2 (n-tiles 0-4 / 5-8; tile 8 = ones col = denom)
// ------------------------------------------------------------------
__global__ void __launch_bounds__(256, 1) k3_gat(const int* __restrict__ adj,
                                                 float* __restrict__ out) {
    extern __shared__ char smem_raw[];
    __half* Ps = reinterpret_cast<__half*>(smem_raw);          // [2][NH][IT][PST]
    __half* Bsm = Ps + 2*NH*IT*PST;                            // [2][NH][JT][BST]
    float2* sAC = reinterpret_cast<float2*>(Bsm + 2*NH*JT*BST);// [NH][IT]
    float*  dsm = reinterpret_cast<float*>(sAC + NH*IT);       // [NH][IT]
    float*  outAcc = dsm + NH*IT;                              // [IT][ND]

    const int tid = threadIdx.x;
    const int w = tid >> 5, lane = tid & 31;
    const int h = w & 3, ns = w >> 2;
    const int i0 = blockIdx.x * IT;

    // ---- init ----
    for (int e = tid; e < IT*ND; e += 256) outAcc[e] = 0.f;
    if (tid < NH*IT) sAC[tid] = g_srcAC[(tid/IT)*NN + i0 + (tid%IT)];
    for (int e = tid; e < 2*NH*JT*8; e += 256) {      // ones column + zero pad cols 64..71
        int c8 = e & 7, r = e >> 3;
        Bsm[r*BST + 64 + c8] = __float2half(c8 == 0 ? 1.f : 0.f);
    }

    float acc[3][5][4] = {};  // [m-tile][n-tile][c-frag]

    auto loadB = [&](int buf, int c){
        int r = tid;                              // 256 rows = 4 heads x 64 j
        int hh = r >> 6, j = r & 63;
        const __half* src = &g_ht16[((size_t)hh*NN + c*JT + j)*ND];
        unsigned d32 = smem_u32(&Bsm[((buf*NH + hh)*JT + j)*BST]);
        #pragma unroll
        for (int s = 0; s < 8; s++)
            asm volatile("cp.async.cg.shared.global [%0], [%1], 16;\n"
                         :: "r"(d32 + s*16), "l"(src + s*8));
    };

    auto pgen = [&](int buf, int c){
        const int j0 = c * JT;
        float4 tb[NH];
        #pragma unroll
        for (int hh = 0; hh < NH; hh++)
            tb[hh] = g_tgtBD4[hh*(NN/2) + c*(JT/2) + lane];
        #pragma unroll
        for (int ii = 0; ii < 6; ii++){
            int i = w + ii*8;
            int2 av = *reinterpret_cast<const int2*>(&adj[(i0+i)*NN + j0 + 2*lane]);
            #pragma unroll
            for (int hh = 0; hh < NH; hh++){
                float2 ac = sAC[hh*IT + i];
                float p0 = fmaxf(ac.x*tb[hh].x, ac.y*tb[hh].y); // exp(leaky(src+tgt)) == max trick
                float p1 = fmaxf(ac.x*tb[hh].z, ac.y*tb[hh].w);
                p0 = av.x ? p0 : 0.f;
                p1 = av.y ? p1 : 0.f;
                *reinterpret_cast<__half2*>(&Ps[((buf*NH + hh)*IT + i)*PST + 2*lane])
                    = __floats2half2_rn(p0, p1);
            }
        }
    };

    auto do_mma = [&](int buf){
        const __half* Pb = &Ps[(buf*NH + h)*IT*PST];
        const __half* Bb = &Bsm[(buf*NH + h)*JT*BST];
        const int rowA = lane & 15, cg = (lane >> 4) * 8;
        #pragma unroll
        for (int ks = 0; ks < 4; ks++){
            uint32_t af[3][4];
            #pragma unroll
            for (int mt = 0; mt < 3; mt++){
                unsigned addr = smem_u32(Pb + (mt*16 + rowA)*PST + ks*16 + cg);
                asm volatile("ldmatrix.sync.aligned.m8n8.x4.shared.b16 {%0,%1,%2,%3}, [%4];\n"
                    : "=r"(af[mt][0]),"=r"(af[mt][1]),"=r"(af[mt][2]),"=r"(af[mt][3])
                    : "r"(addr));
            }
            uint32_t bf[5][2];
            #pragma unroll
            for (int nt = 0; nt < 5; nt++){
                int ntg = ns*5 + nt;
                if (ntg < 9){
                    unsigned addr = smem_u32(Bb + (ks*16 + rowA)*BST + ntg*8);
                    asm volatile("ldmatrix.sync.aligned.m8n8.x2.trans.shared.b16 {%0,%1}, [%2];\n"
                        : "=r"(bf[nt][0]),"=r"(bf[nt][1]) : "r"(addr));
                }
            }
            #pragma unroll
            for (int mt = 0; mt < 3; mt++)
                #pragma unroll
                for (int nt = 0; nt < 5; nt++){
                    if (ns*5 + nt < 9)
                        asm volatile(
                          "mma.sync.aligned.m16n8k16.row.col.f32.f16.f16.f32 "
                          "{%0,%1,%2,%3}, {%4,%5,%6,%7}, {%8,%9}, {%0,%1,%2,%3};\n"
                          : "+f"(acc[mt][nt][0]),"+f"(acc[mt][nt][1]),
                            "+f"(acc[mt][nt][2]),"+f"(acc[mt][nt][3])
                          : "r"(af[mt][0]),"r"(af[mt][1]),"r"(af[mt][2]),"r"(af[mt][3]),
                            "r"(bf[nt][0]),"r"(bf[nt][1]));
                }
        }
    };

    // ---- prologue ----
    loadB(0, 0);
    asm volatile("cp.async.commit_group;\n" ::: "memory");
    __syncthreads();              // sAC / ones-cols / outAcc ready
    pgen(0, 0);

    // ---- main pipeline ----
    for (int c = 0; c < NCHUNK; ++c) {
        asm volatile("cp.async.wait_group 0;\n" ::: "memory");   // B(c) landed (this thread)
        __syncthreads();          // all copies + P(c) visible; MMA(c-1) done with old buffers
        if (c + 1 < NCHUNK) loadB((c+1)&1, c+1);
        asm volatile("cp.async.commit_group;\n" ::: "memory");
        if (c + 1 < NCHUNK) pgen((c+1)&1, c+1);                  // fma pipe...
        do_mma(c & 1);                                           // ...overlaps tensor pipe
    }

    // ---- epilogue ----
    __syncthreads();
    if (ns == 1 && (lane & 3) == 0){        // denom = ones-column (global n-tile 8, local nt 3)
        #pragma unroll
        for (int mt = 0; mt < 3; mt++){
            dsm[h*IT + mt*16 + (lane>>2)]     = acc[mt][3][0];
            dsm[h*IT + mt*16 + (lane>>2) + 8] = acc[mt][3][2];
        }
    }
    __syncthreads();
    if (tid < NH*IT) dsm[tid] = 1.0f / dsm[tid];
    __syncthreads();
    #pragma unroll
    for (int mt = 0; mt < 3; mt++){
        int r0 = mt*16 + (lane>>2), r1 = r0 + 8;
        float ri0 = dsm[h*IT + r0] * 0.25f;
        float ri1 = dsm[h*IT + r1] * 0.25f;
        #pragma unroll
        for (int nt = 0; nt < 5; nt++){
            int ntg = ns*5 + nt;
            if (ntg < 8){
                int col = ntg*8 + 2*(lane & 3);
                atomicAdd(&outAcc[r0*ND + col],     acc[mt][nt][0]*ri0);
                atomicAdd(&outAcc[r0*ND + col + 1], acc[mt][nt][1]*ri0);
                atomicAdd(&outAcc[r1*ND + col],     acc[mt][nt][2]*ri1);
                atomicAdd(&outAcc[r1*ND + col + 1], acc[mt][nt][3]*ri1);
            }
        }
    }
    __syncthreads();
    for (int e = tid; e < IT*ND; e += 256)
        out[(size_t)i0*ND + e] = outAcc[e];
}

// ------------------------------------------------------------------
#define SMEM3 ((2*NH*IT*PST + 2*NH*JT*BST)*2 + (NH*IT)*8 + (NH*IT)*4 + IT*ND*4)

extern "C" void kernel_launch(void* const* d_in, const int* in_sizes, int n_in,
                              void* d_out, int out_size) {
    const float* h   = (const float*)d_in[0];
    const int*   adj = (const int*)d_in[1];
    const float* W   = (const float*)d_in[2];
    const float* a   = (const float*)d_in[3];
    float* out = (float*)d_out;

    cudaFuncSetAttribute(k3_gat, cudaFuncAttributeMaxDynamicSharedMemorySize, SMEM3);

    k1_gemm<<<dim3(4, 96), 256>>>(h, W);
    k2_srctgt<<<(NH*NN)/8, 256>>>(a);
    k3_gat<<<NN/IT, 256, SMEM3>>>(adj, out);
}

// round 7
// speedup vs baseline: 1.4349x; 1.4349x over previous
#include <cuda_runtime.h>
#include <cuda_fp16.h>
#include <cstdint>

#define NN 6144
#define NF 256
#define NH 4
#define ND 64
#define IT 48            // rows per CTA (6144/48 = 128 CTAs)
#define JT 64            // j-chunk
#define NCHUNK (NN/JT)   // 96
#define PST 72           // P smem row stride (halves)
#define BST 88           // B smem row stride (halves), 72 cols + pad

// scratch (__device__ globals allowed)
__device__ __half  g_ht16[NH*NN*ND];        // [h][n][d] fp16
__device__ __half2 g_srcAC2[NH*NN];         // (e^src, e^{0.2 src})
__device__ __half2 g_tgtBD2[NH*NN];         // (e^tgt, e^{0.2 tgt})

__device__ __forceinline__ unsigned smem_u32(const void* p){
    return (unsigned)__cvta_generic_to_shared(p);
}
__device__ __forceinline__ unsigned h2u(__half2 v){ return *reinterpret_cast<unsigned*>(&v); }
__device__ __forceinline__ __half2 u2h(unsigned v){ return *reinterpret_cast<__half2*>(&v); }

// ------------------------------------------------------------------
// kernel 1: ht = h @ W (fp32 accum), store fp16. grid (4, 48), block 256.
// C tile: 128 (n) x 64 (m = head*64 + d). 8x4 per thread.
// ------------------------------------------------------------------
__global__ void k1_gemm(const float* __restrict__ h, const float* __restrict__ W) {
    __shared__ float As[16][128];  // [k][n]
    __shared__ float Bs[16][64];   // [k][m]
    const int tid = threadIdx.x;
    const int tx = tid & 15, ty = tid >> 4;
    const int m0 = blockIdx.x * 64;
    const int n0 = blockIdx.y * 128;
    float acc[8][4] = {};
    for (int k0 = 0; k0 < NF; k0 += 16) {
        {   // h tile -> transposed
            int n = tid >> 1, kh = (tid & 1) * 8;
            float4 v0 = *reinterpret_cast<const float4*>(&h[(n0+n)*NF + k0 + kh]);
            float4 v1 = *reinterpret_cast<const float4*>(&h[(n0+n)*NF + k0 + kh + 4]);
            As[kh+0][n]=v0.x; As[kh+1][n]=v0.y; As[kh+2][n]=v0.z; As[kh+3][n]=v0.w;
            As[kh+4][n]=v1.x; As[kh+5][n]=v1.y; As[kh+6][n]=v1.z; As[kh+7][n]=v1.w;
        }
        {   // W tile
            int k = tid >> 4, mq = tid & 15;
            float4 v = *reinterpret_cast<const float4*>(&W[(k0+k)*NF + m0 + mq*4]);
            *reinterpret_cast<float4*>(&Bs[k][mq*4]) = v;
        }
        __syncthreads();
        #pragma unroll
        for (int kk = 0; kk < 16; kk++) {
            float4 a0 = *reinterpret_cast<const float4*>(&As[kk][ty*8]);
            float4 a1 = *reinterpret_cast<const float4*>(&As[kk][ty*8+4]);
            float4 b4 = *reinterpret_cast<const float4*>(&Bs[kk][tx*4]);
            float av[8] = {a0.x,a0.y,a0.z,a0.w,a1.x,a1.y,a1.z,a1.w};
            float bv[4] = {b4.x,b4.y,b4.z,b4.w};
            #pragma unroll
            for (int i=0;i<8;i++)
                #pragma unroll
                for (int j=0;j<4;j++) acc[i][j] += av[i]*bv[j];
        }
        __syncthreads();
    }
    const int head = blockIdx.x;
    #pragma unroll
    for (int i=0;i<8;i++){
        int n = n0 + ty*8 + i;
        __half* dst = &g_ht16[((size_t)head*NN + n)*ND + tx*4];
        #pragma unroll
        for (int j=0;j<4;j+=2)
            *reinterpret_cast<__half2*>(dst + j) = __floats2half2_rn(acc[i][j], acc[i][j+1]);
    }
}

// ------------------------------------------------------------------
// kernel 2: per (head,node) logits -> 4 exps, packed half2
// ------------------------------------------------------------------
__global__ void k2_srctgt(const float* __restrict__ a) {
    const int w = threadIdx.x >> 5, lane = threadIdx.x & 31;
    const int p = blockIdx.x * 8 + w;      // p = h*NN + n
    const int hh = p / NN;
    __half2 x = reinterpret_cast<const __half2*>(&g_ht16[(size_t)p*ND])[lane];
    float2 xf = __half22float2(x);
    float2 as = *reinterpret_cast<const float2*>(&a[hh*2*ND + 2*lane]);
    float2 at = *reinterpret_cast<const float2*>(&a[hh*2*ND + ND + 2*lane]);
    float s = xf.x*as.x + xf.y*as.y;
    float t = xf.x*at.x + xf.y*at.y;
    #pragma unroll
    for (int off = 16; off; off >>= 1){
        s += __shfl_xor_sync(0xffffffffu, s, off);
        t += __shfl_xor_sync(0xffffffffu, t, off);
    }
    if (lane == 0) {
        g_srcAC2[p] = __floats2half2_rn(expf(s), expf(0.2f*s));
        g_tgtBD2[p] = __floats2half2_rn(expf(t), expf(0.2f*t));
    }
}

// ------------------------------------------------------------------
// kernel 3: flash-style GAT. grid 128, block 256 (8 warps).
// warp w: head = w&3, n-set = w>>2 (n-tiles 0-4 / 5-8; tile 8 = ones col)
// ------------------------------------------------------------------
__global__ void __launch_bounds__(256, 1) k3_gat(const int* __restrict__ adj,
                                                 float* __restrict__ out) {
    extern __shared__ char smem_raw[];
    __half* Ps = reinterpret_cast<__half*>(smem_raw);          // [2][NH][IT][PST]
    __half* Bsm = Ps + 2*NH*IT*PST;                            // [2][NH][JT][BST]
    float*  dsm = reinterpret_cast<float*>(Bsm + 2*NH*JT*BST); // [NH][IT]
    float*  outAcc = dsm + NH*IT;                              // [IT][ND]

    const int tid = threadIdx.x;
    const int w = tid >> 5, lane = tid & 31;
    const int h = w & 3, ns = w >> 2;
    const int i0 = blockIdx.x * IT;

    // ---- init ----
    for (int e = tid; e < IT*ND; e += 256) outAcc[e] = 0.f;
    for (int e = tid; e < 2*NH*JT*8; e += 256) {      // ones column + zero pad cols 64..71
        int c8 = e & 7, r = e >> 3;
        Bsm[r*BST + 64 + c8] = __float2half(c8 == 0 ? 1.f : 0.f);
    }

    // resident per-(row,head) src factors (A,C) packed
    __half2 AC[6][NH];
    #pragma unroll
    for (int ii = 0; ii < 6; ii++)
        #pragma unroll
        for (int hh = 0; hh < NH; hh++)
            AC[ii][hh] = g_srcAC2[hh*NN + i0 + w + ii*8];

    float acc[3][5][4] = {};  // [m-tile][n-tile][c-frag]

    const size_t rowbase = (size_t)(i0 + w)*NN + 2*lane;

    auto loadAdj = [&](int2* dst, int cc){
        #pragma unroll
        for (int ii = 0; ii < 6; ii++)
            dst[ii] = __ldcs(reinterpret_cast<const int2*>(adj + rowbase + (size_t)ii*8*NN + cc*JT));
    };
    auto loadTgt = [&](uint2* dst, int cc){
        #pragma unroll
        for (int hh = 0; hh < NH; hh++)
            dst[hh] = __ldg(reinterpret_cast<const uint2*>(g_tgtBD2 + hh*NN + cc*JT + 2*lane));
    };

    auto loadB = [&](int buf, int c){
        int r = tid;                              // 256 rows = 4 heads x 64 j
        int hh = r >> 6, j = r & 63;
        const __half* src = &g_ht16[((size_t)hh*NN + c*JT + j)*ND];
        unsigned d32 = smem_u32(&Bsm[((buf*NH + hh)*JT + j)*BST]);
        #pragma unroll
        for (int s = 0; s < 8; s++)
            asm volatile("cp.async.cg.shared.global [%0], [%1], 16;\n"
                         :: "r"(d32 + s*16), "l"(src + s*8));
    };

    auto pgen = [&](int buf, const int2* A, const uint2* T){
        unsigned mk[6];
        #pragma unroll
        for (int ii = 0; ii < 6; ii++)
            mk[ii] = (unsigned)A[ii].x*0x3C00u + (unsigned)A[ii].y*0x3C000000u;
        #pragma unroll
        for (int hh = 0; hh < NH; hh++){
            __half2 bd0 = u2h(T[hh].x), bd1 = u2h(T[hh].y);
            __half* pb = &Ps[(buf*NH + hh)*IT*PST];
            #pragma unroll
            for (int ii = 0; ii < 6; ii++){
                __half2 t0 = __hmul2(AC[ii][hh], bd0);   // (A*B0, C*D0)
                __half2 t1 = __hmul2(AC[ii][hh], bd1);
                __half p0 = __hmax(__low2half(t0), __high2half(t0));
                __half p1 = __hmax(__low2half(t1), __high2half(t1));
                __half2 p = __hmul2(__halves2half2(p0, p1), u2h(mk[ii]));
                *reinterpret_cast<__half2*>(&pb[(w + ii*8)*PST + 2*lane]) = p;
            }
        }
    };

    auto do_mma = [&](int buf){
        const __half* Pb = &Ps[(buf*NH + h)*IT*PST];
        const __half* Bb = &Bsm[(buf*NH + h)*JT*BST];
        const int rowA = lane & 15, cg = (lane >> 4) * 8;
        #pragma unroll
        for (int ks = 0; ks < 4; ks++){
            uint32_t af[3][4];
            #pragma unroll
            for (int mt = 0; mt < 3; mt++){
                unsigned addr = smem_u32(Pb + (mt*16 + rowA)*PST + ks*16 + cg);
                asm volatile("ldmatrix.sync.aligned.m8n8.x4.shared.b16 {%0,%1,%2,%3}, [%4];\n"
                    : "=r"(af[mt][0]),"=r"(af[mt][1]),"=r"(af[mt][2]),"=r"(af[mt][3])
                    : "r"(addr));
            }
            uint32_t bf[5][2];
            #pragma unroll
            for (int nt = 0; nt < 5; nt++){
                int ntg = ns*5 + nt;
                if (ntg < 9){
                    unsigned addr = smem_u32(Bb + (ks*16 + rowA)*BST + ntg*8);
                    asm volatile("ldmatrix.sync.aligned.m8n8.x2.trans.shared.b16 {%0,%1}, [%2];\n"
                        : "=r"(bf[nt][0]),"=r"(bf[nt][1]) : "r"(addr));
                }
            }
            #pragma unroll
            for (int mt = 0; mt < 3; mt++)
                #pragma unroll
                for (int nt = 0; nt < 5; nt++){
                    if (ns*5 + nt < 9)
                        asm volatile(
                          "mma.sync.aligned.m16n8k16.row.col.f32.f16.f16.f32 "
                          "{%0,%1,%2,%3}, {%4,%5,%6,%7}, {%8,%9}, {%0,%1,%2,%3};\n"
                          : "+f"(acc[mt][nt][0]),"+f"(acc[mt][nt][1]),
                            "+f"(acc[mt][nt][2]),"+f"(acc[mt][nt][3])
                          : "r"(af[mt][0]),"r"(af[mt][1]),"r"(af[mt][2]),"r"(af[mt][3]),
                            "r"(bf[nt][0]),"r"(bf[nt][1]));
                }
        }
    };

    // ---- prologue ----
    int2 curA[6]; uint2 curT[NH];
    loadAdj(curA, 0); loadTgt(curT, 0);
    loadB(0, 0);
    asm volatile("cp.async.commit_group;\n" ::: "memory");
    __syncthreads();              // ones-cols / outAcc ready
    pgen(0, curA, curT);          // P(0)
    loadAdj(curA, 1); loadTgt(curT, 1);   // data for chunk 1

    // ---- main pipeline: at iter c, cur holds chunk c+1 ----
    for (int c = 0; c < NCHUNK; ++c) {
        asm volatile("cp.async.wait_group 0;\n" ::: "memory");   // B(c) landed
        __syncthreads();          // all B copies + P(c) visible; MMA(c-1) done
        if (c + 1 < NCHUNK) loadB((c+1)&1, c+1);
        asm volatile("cp.async.commit_group;\n" ::: "memory");

        int2 nxtA[6]; uint2 nxtT[NH];
        if (c + 2 < NCHUNK){ loadAdj(nxtA, c+2); loadTgt(nxtT, c+2); }
        if (c + 1 < NCHUNK) pgen((c+1)&1, curA, curT);           // fma pipe...
        do_mma(c & 1);                                           // ...overlaps tensor pipe
        if (c + 2 < NCHUNK){
            #pragma unroll
            for (int ii=0; ii<6; ii++) curA[ii] = nxtA[ii];
            #pragma unroll
            for (int hh=0; hh<NH; hh++) curT[hh] = nxtT[hh];
        }
    }

    // ---- epilogue ----
    __syncthreads();
    if (ns == 1 && (lane & 3) == 0){        // denom = ones-column (n-tile 8, local nt 3)
        #pragma unroll
        for (int mt = 0; mt < 3; mt++){
            dsm[h*IT + mt*16 + (lane>>2)]     = acc[mt][3][0];
            dsm[h*IT + mt*16 + (lane>>2) + 8] = acc[mt][3][2];
        }
    }
    __syncthreads();
    if (tid < NH*IT) dsm[tid] = 1.0f / dsm[tid];
    __syncthreads();
    #pragma unroll
    for (int mt = 0; mt < 3; mt++){
        int r0 = mt*16 + (lane>>2), r1 = r0 + 8;
        float ri0 = dsm[h*IT + r0] * 0.25f;
        float ri1 = dsm[h*IT + r1] * 0.25f;
        #pragma unroll
        for (int nt = 0; nt < 5; nt++){
            int ntg = ns*5 + nt;
            if (ntg < 8){
                int col = ntg*8 + 2*(lane & 3);
                atomicAdd(&outAcc[r0*ND + col],     acc[mt][nt][0]*ri0);
                atomicAdd(&outAcc[r0*ND + col + 1], acc[mt][nt][1]*ri0);
                atomicAdd(&outAcc[r1*ND + col],     acc[mt][nt][2]*ri1);
                atomicAdd(&outAcc[r1*ND + col + 1], acc[mt][nt][3]*ri1);
            }
        }
    }
    __syncthreads();
    for (int e = tid; e < IT*ND; e += 256)
        out[(size_t)i0*ND + e] = outAcc[e];
}

// ------------------------------------------------------------------
#define SMEM3 ((2*NH*IT*PST + 2*NH*JT*BST)*2 + (NH*IT)*4 + IT*ND*4)

extern "C" void kernel_launch(void* const* d_in, const int* in_sizes, int n_in,
                              void* d_out, int out_size) {
    const float* h   = (const float*)d_in[0];
    const int*   adj = (const int*)d_in[1];
    const float* W   = (const float*)d_in[2];
    const float* a   = (const float*)d_in[3];
    float* out = (float*)d_out;

    cudaFuncSetAttribute(k3_gat, cudaFuncAttributeMaxDynamicSharedMemorySize, SMEM3);

    k1_gemm<<<dim3(4, 48), 256>>>(h, W);
    k2_srctgt<<<(NH*NN)/8, 256>>>(a);
    k3_gat<<<NN/IT, 256, SMEM3>>>(adj, out);
}

// round 8
// speedup vs baseline: 2.8855x; 2.0109x over previous
#include <cuda_runtime.h>
#include <cuda_fp16.h>
#include <cstdint>

#define NN 6144
#define NF 256
#define NH 4
#define ND 64
#define IB 128               // i-rows per CTA
#define JSP 3                // j splits
#define JL 2048              // j per CTA
#define NC2 32               // chunks of 64

// ---- scratch ----
__device__ __align__(256) __half  g_ht16[NH*NN*ND];   // [h][n][d]
__device__ __align__(256) __half2 g_srcAC2[NH*NN];    // (e^src, e^{0.2src})
__device__ __align__(256) __half2 g_tgtBD2[NH*NN];    // (e^tgt, e^{0.2tgt})
__device__ __align__(256) float   g_num[JSP*NH*NN*ND];
__device__ __align__(256) float   g_den[JSP*NH*NN];

// k3 smem byte offsets
#define POFF(b,h)  (((b)*4+(h))*16384)                 // 128 rows x 128B, swizzled
#define BOFF(b,h)  (131072 + ((b)*4+(h))*8192)         // 64 rows x 128B, swizzled
#define TOFF(s,h)  (196608 + ((s)*4+(h))*256)          // 64 half2
#define SMEM3      200704

__device__ __forceinline__ unsigned smem_u32(const void* p){
    return (unsigned)__cvta_generic_to_shared(p);
}
__device__ __forceinline__ unsigned h2u(__half2 v){ return *reinterpret_cast<unsigned*>(&v); }
__device__ __forceinline__ __half2 u2h(unsigned v){ return *reinterpret_cast<__half2*>(&v); }

// ------------------------------------------------------------------
// k1h: ht = h @ W via fp16 mma (fp32 accum). grid (4 heads, 48), block 256.
// ------------------------------------------------------------------
#define HS_ST 264   // halves per row (256+8)
#define WS_ST 72    // halves per row (64+8)
#define SMEM1 ((128*HS_ST + 256*WS_ST)*2)

__global__ void __launch_bounds__(256) k1h_gemm(const float* __restrict__ h,
                                                const float* __restrict__ W) {
    extern __shared__ char smem[];
    __half* Hs = reinterpret_cast<__half*>(smem);            // [128][HS_ST]
    __half* Ws = Hs + 128*HS_ST;                             // [256][WS_ST]
    const int tid = threadIdx.x, w = tid >> 5, lane = tid & 31;
    const int head = blockIdx.x;
    const int n0 = blockIdx.y * 128;

    {   // load h rows (convert fp32->fp16)
        int row = tid >> 1, ch = (tid & 1) * 128;
        #pragma unroll 8
        for (int q = 0; q < 32; q++){
            float4 v = *reinterpret_cast<const float4*>(&h[(size_t)(n0+row)*NF + ch + q*4]);
            __half2 lo = __floats2half2_rn(v.x, v.y), hi = __floats2half2_rn(v.z, v.w);
            uint2 o; o.x = h2u(lo); o.y = h2u(hi);
            *reinterpret_cast<uint2*>(&Hs[row*HS_ST + ch + q*4]) = o;
        }
    }
    {   // load W column block for this head
        int k = tid;
        #pragma unroll 4
        for (int q = 0; q < 16; q++){
            float4 v = *reinterpret_cast<const float4*>(&W[(size_t)k*NF + head*ND + q*4]);
            __half2 lo = __floats2half2_rn(v.x, v.y), hi = __floats2half2_rn(v.z, v.w);
            uint2 o; o.x = h2u(lo); o.y = h2u(hi);
            *reinterpret_cast<uint2*>(&Ws[k*WS_ST + q*4]) = o;
        }
    }
    __syncthreads();

    float acc[8][4] = {};
    #pragma unroll
    for (int ks = 0; ks < 16; ks++){
        uint32_t af[4];
        {
            int r = w*16 + (lane & 15);
            unsigned addr = smem_u32(Hs) + (unsigned)(r*HS_ST*2 + ks*32 + (lane>>4)*16);
            asm volatile("ldmatrix.sync.aligned.m8n8.x4.shared.b16 {%0,%1,%2,%3}, [%4];\n"
                : "=r"(af[0]),"=r"(af[1]),"=r"(af[2]),"=r"(af[3]) : "r"(addr));
        }
        uint32_t bf[8][2];
        #pragma unroll
        for (int nt = 0; nt < 8; nt++){
            int kr = ks*16 + (lane & 15);
            unsigned addr = smem_u32(Ws) + (unsigned)(kr*WS_ST*2 + nt*16);
            asm volatile("ldmatrix.sync.aligned.m8n8.x2.trans.shared.b16 {%0,%1}, [%2];\n"
                : "=r"(bf[nt][0]),"=r"(bf[nt][1]) : "r"(addr));
        }
        #pragma unroll
        for (int nt = 0; nt < 8; nt++)
            asm volatile(
              "mma.sync.aligned.m16n8k16.row.col.f32.f16.f16.f32 "
              "{%0,%1,%2,%3}, {%4,%5,%6,%7}, {%8,%9}, {%0,%1,%2,%3};\n"
              : "+f"(acc[nt][0]),"+f"(acc[nt][1]),"+f"(acc[nt][2]),"+f"(acc[nt][3])
              : "r"(af[0]),"r"(af[1]),"r"(af[2]),"r"(af[3]),
                "r"(bf[nt][0]),"r"(bf[nt][1]));
    }

    int r0 = n0 + w*16 + (lane >> 2);
    #pragma unroll
    for (int nt = 0; nt < 8; nt++){
        int d = nt*8 + (lane & 3)*2;
        *reinterpret_cast<__half2*>(&g_ht16[((size_t)head*NN + r0)*ND + d])
            = __floats2half2_rn(acc[nt][0], acc[nt][1]);
        *reinterpret_cast<__half2*>(&g_ht16[((size_t)head*NN + r0 + 8)*ND + d])
            = __floats2half2_rn(acc[nt][2], acc[nt][3]);
    }
}

// ------------------------------------------------------------------
// k2: per (head,node) logits -> 4 exps, packed half2
// ------------------------------------------------------------------
__global__ void k2_srctgt(const float* __restrict__ a) {
    const int w = threadIdx.x >> 5, lane = threadIdx.x & 31;
    const int p = blockIdx.x * 8 + w;      // p = h*NN + n
    const int hh = p / NN;
    __half2 x = reinterpret_cast<const __half2*>(&g_ht16[(size_t)p*ND])[lane];
    float2 xf = __half22float2(x);
    float2 as = *reinterpret_cast<const float2*>(&a[hh*2*ND + 2*lane]);
    float2 at = *reinterpret_cast<const float2*>(&a[hh*2*ND + ND + 2*lane]);
    float s = xf.x*as.x + xf.y*as.y;
    float t = xf.x*at.x + xf.y*at.y;
    #pragma unroll
    for (int off = 16; off; off >>= 1){
        s += __shfl_xor_sync(0xffffffffu, s, off);
        t += __shfl_xor_sync(0xffffffffu, t, off);
    }
    if (lane == 0) {
        g_srcAC2[p] = __floats2half2_rn(expf(s), expf(0.2f*s));
        g_tgtBD2[p] = __floats2half2_rn(expf(t), expf(0.2f*t));
    }
}

// ------------------------------------------------------------------
// k3: flash GAT, 144 CTAs (48 ib x 3 split), 256 threads / 8 warps.
// warp w: head = w&3, m-half = w>>2 (64 rows). N=64, den in fp32.
// ------------------------------------------------------------------
__global__ void __launch_bounds__(256, 1) k3_gat(const int* __restrict__ adj){
    extern __shared__ char smem[];
    const unsigned sbase = smem_u32(smem);
    const int tid = threadIdx.x, w = tid >> 5, lane = tid & 31;
    const int h = w & 3, mh = w >> 2;
    const int ib = blockIdx.x / 3, split = blockIdx.x % 3;
    const int i0 = ib * IB, j0 = split * JL;
    const int rg = tid >> 2, jg = tid & 3;    // rows 2rg,2rg+1 ; j block jg*16

    __half2 AC[2][NH];
    #pragma unroll
    for (int rr = 0; rr < 2; rr++)
        #pragma unroll
        for (int hh = 0; hh < NH; hh++)
            AC[rr][hh] = g_srcAC2[hh*NN + i0 + 2*rg + rr];

    float den[2][NH] = {};
    float acc[4][8][4] = {};     // [mt][nt][frag]

    auto loadB = [&](int buf, int c){
        #pragma unroll
        for (int t = 0; t < 8; t++){
            int idx = tid + t*256;
            int hh = idx >> 9, rw = (idx >> 3) & 63, s = idx & 7;
            const __half* src = &g_ht16[((size_t)hh*NN + j0 + c*64 + rw)*ND + s*8];
            unsigned dst = sbase + BOFF(buf,hh) + rw*128 + ((s*16) ^ ((rw&7)<<4));
            asm volatile("cp.async.cg.shared.global [%0], [%1], 16;\n" :: "r"(dst), "l"(src));
        }
    };
    auto loadTgt = [&](int slot, int c){
        if (tid < 64){
            int hh = tid >> 4, q = tid & 15;
            const __half2* src = g_tgtBD2 + hh*NN + j0 + c*64 + q*4;
            unsigned dst = sbase + TOFF(slot,hh) + q*16;
            asm volatile("cp.async.cg.shared.global [%0], [%1], 16;\n" :: "r"(dst), "l"(src));
        }
    };
    auto loadAdj = [&](int4* dst, int cc){
        #pragma unroll
        for (int rr = 0; rr < 2; rr++){
            const int4* base = reinterpret_cast<const int4*>(
                adj + (size_t)(i0 + 2*rg + rr)*NN + j0 + cc*64 + jg*16);
            #pragma unroll
            for (int q = 0; q < 4; q++) dst[rr*4+q] = __ldcs(base + q);
        }
    };

    auto pgen = [&](int buf, int slot, const int4* adjr){
        unsigned mk[2][8];
        #pragma unroll
        for (int rr = 0; rr < 2; rr++)
            #pragma unroll
            for (int p = 0; p < 8; p++){
                int4 aq = adjr[rr*4 + (p>>1)];
                int a0 = (p&1) ? aq.z : aq.x;
                int a1 = (p&1) ? aq.w : aq.y;
                mk[rr][p] = (unsigned)a0*0x3C00u + (unsigned)a1*0x3C000000u;
            }
        #pragma unroll
        for (int hh = 0; hh < NH; hh++){
            const uint4* tp = reinterpret_cast<const uint4*>(smem + TOFF(slot,hh) - 0 + jg*64);
            uint4 T0 = tp[0], T1 = tp[1], T2 = tp[2], T3 = tp[3];
            unsigned tv[16] = {T0.x,T0.y,T0.z,T0.w, T1.x,T1.y,T1.z,T1.w,
                               T2.x,T2.y,T2.z,T2.w, T3.x,T3.y,T3.z,T3.w};
            #pragma unroll
            for (int rr = 0; rr < 2; rr++){
                const int r = 2*rg + rr;
                __half2 ac = AC[rr][hh];
                unsigned o[8];
                float dsum = 0.f;
                #pragma unroll
                for (int p = 0; p < 8; p++){
                    __half2 t0 = __hmul2(ac, u2h(tv[2*p]));
                    __half2 t1 = __hmul2(ac, u2h(tv[2*p+1]));
                    __half p0 = __hmax(__low2half(t0), __high2half(t0));
                    __half p1 = __hmax(__low2half(t1), __high2half(t1));
                    __half2 pm = __hmul2(__halves2half2(p0, p1), u2h(mk[rr][p]));
                    o[p] = h2u(pm);
                    float2 f = __half22float2(pm);
                    dsum += f.x + f.y;
                }
                den[rr][hh] += dsum;
                unsigned sw = (unsigned)((r&7)<<4);
                char* pb = smem + POFF(buf,hh) + r*128;
                uint4 o0; o0.x=o[0]; o0.y=o[1]; o0.z=o[2]; o0.w=o[3];
                uint4 o1; o1.x=o[4]; o1.y=o[5]; o1.z=o[6]; o1.w=o[7];
                *reinterpret_cast<uint4*>(pb + (((unsigned)(jg*32))      ^ sw)) = o0;
                *reinterpret_cast<uint4*>(pb + (((unsigned)(jg*32 + 16)) ^ sw)) = o1;
            }
        }
    };

    auto do_mma = [&](int buf){
        const unsigned PB = sbase + POFF(buf,h);
        const unsigned BB = sbase + BOFF(buf,h);
        #pragma unroll
        for (int ks = 0; ks < 4; ks++){
            uint32_t af[4][4];
            #pragma unroll
            for (int mt = 0; mt < 4; mt++){
                int r = mh*64 + mt*16 + (lane & 15);
                unsigned cb = (unsigned)(ks*32 + (lane>>4)*16);
                unsigned addr = PB + r*128 + (cb ^ ((r&7)<<4));
                asm volatile("ldmatrix.sync.aligned.m8n8.x4.shared.b16 {%0,%1,%2,%3}, [%4];\n"
                    : "=r"(af[mt][0]),"=r"(af[mt][1]),"=r"(af[mt][2]),"=r"(af[mt][3])
                    : "r"(addr));
            }
            uint32_t bf[8][2];
            #pragma unroll
            for (int nt = 0; nt < 8; nt++){
                int jr = ks*16 + (lane & 15);
                unsigned addr = BB + jr*128 + (((unsigned)(nt*16)) ^ ((jr&7)<<4));
                asm volatile("ldmatrix.sync.aligned.m8n8.x2.trans.shared.b16 {%0,%1}, [%2];\n"
                    : "=r"(bf[nt][0]),"=r"(bf[nt][1]) : "r"(addr));
            }
            #pragma unroll
            for (int mt = 0; mt < 4; mt++)
                #pragma unroll
                for (int nt = 0; nt < 8; nt++)
                    asm volatile(
                      "mma.sync.aligned.m16n8k16.row.col.f32.f16.f16.f32 "
                      "{%0,%1,%2,%3}, {%4,%5,%6,%7}, {%8,%9}, {%0,%1,%2,%3};\n"
                      : "+f"(acc[mt][nt][0]),"+f"(acc[mt][nt][1]),
                        "+f"(acc[mt][nt][2]),"+f"(acc[mt][nt][3])
                      : "r"(af[mt][0]),"r"(af[mt][1]),"r"(af[mt][2]),"r"(af[mt][3]),
                        "r"(bf[nt][0]),"r"(bf[nt][1]));
        }
    };

    // ---- prologue ----
    int4 adjr[8];
    loadTgt(0, 0); loadTgt(1, 1); loadB(0, 0);
    asm volatile("cp.async.commit_group;\n" ::: "memory");
    loadAdj(adjr, 0);
    asm volatile("cp.async.wait_group 0;\n" ::: "memory");
    __syncthreads();
    pgen(0, 0, adjr);                       // P(0)

    // ---- main loop ----
    for (int c = 0; c < NC2; ++c){
        const int buf = c & 1;
        asm volatile("cp.async.wait_group 0;\n" ::: "memory");  // B(c), tgt(c+1) landed
        __syncthreads();                                        // + P(c) visible
        if (c + 1 < NC2) loadB(buf ^ 1, c + 1);
        if (c + 2 < NC2) loadTgt((c + 2) & 3, c + 2);
        asm volatile("cp.async.commit_group;\n" ::: "memory");
        if (c + 1 < NC2) loadAdj(adjr, c + 1);   // lands under mma
        do_mma(buf);                              // tensor pipe first
        if (c + 1 < NC2) pgen(buf ^ 1, (c + 1) & 3, adjr);
    }

    // ---- epilogue: den lane-reduce + partial writes ----
    #pragma unroll
    for (int rr = 0; rr < 2; rr++)
        #pragma unroll
        for (int hh = 0; hh < NH; hh++){
            float v = den[rr][hh];
            v += __shfl_xor_sync(0xffffffffu, v, 1);
            v += __shfl_xor_sync(0xffffffffu, v, 2);
            if (jg == 0)
                g_den[((size_t)split*NH + hh)*NN + i0 + 2*rg + rr] = v;
        }
    #pragma unroll
    for (int mt = 0; mt < 4; mt++){
        int r0 = i0 + mh*64 + mt*16 + (lane >> 2);
        #pragma unroll
        for (int nt = 0; nt < 8; nt++){
            int d = nt*8 + (lane & 3)*2;
            float2 v0; v0.x = acc[mt][nt][0]; v0.y = acc[mt][nt][1];
            float2 v1; v1.x = acc[mt][nt][2]; v1.y = acc[mt][nt][3];
            *reinterpret_cast<float2*>(&g_num[(((size_t)split*NH + h)*NN + r0)*ND + d]) = v0;
            *reinterpret_cast<float2*>(&g_num[(((size_t)split*NH + h)*NN + r0 + 8)*ND + d]) = v1;
        }
    }
}

// ------------------------------------------------------------------
// k4: combine split partials, divide, mean over heads
// ------------------------------------------------------------------
__global__ void k4_reduce(float* __restrict__ out){
    const int i = blockIdx.x, d = threadIdx.x;     // 64 threads
    __shared__ float rinv[NH];
    if (d < NH){
        float s = 0.f;
        #pragma unroll
        for (int sp = 0; sp < JSP; sp++) s += g_den[((size_t)sp*NH + d)*NN + i];
        rinv[d] = 1.f / s;
    }
    __syncthreads();
    float acc = 0.f;
    #pragma unroll
    for (int hh = 0; hh < NH; hh++){
        float s = 0.f;
        #pragma unroll
        for (int sp = 0; sp < JSP; sp++)
            s += g_num[(((size_t)sp*NH + hh)*NN + i)*ND + d];
        acc += s * rinv[hh];
    }
    out[(size_t)i*ND + d] = acc * 0.25f;
}

// ------------------------------------------------------------------
extern "C" void kernel_launch(void* const* d_in, const int* in_sizes, int n_in,
                              void* d_out, int out_size) {
    const float* h   = (const float*)d_in[0];
    const int*   adj = (const int*)d_in[1];
    const float* W   = (const float*)d_in[2];
    const float* a   = (const float*)d_in[3];
    float* out = (float*)d_out;

    cudaFuncSetAttribute(k1h_gemm, cudaFuncAttributeMaxDynamicSharedMemorySize, SMEM1);
    cudaFuncSetAttribute(k3_gat,  cudaFuncAttributeMaxDynamicSharedMemorySize, SMEM3);

    k1h_gemm<<<dim3(4, 48), 256, SMEM1>>>(h, W);
    k2_srctgt<<<(NH*NN)/8, 256>>>(a);
    k3_gat<<<48*JSP, 256, SMEM3>>>(adj);
    k4_reduce<<<NN, ND>>>(out);
}